// round 5
// baseline (speedup 1.0000x reference)
#include <cuda_runtime.h>

#define B_ 8
#define P_ 57744
#define C_ 81
#define N_ 20
#define ROWS_ (B_ * P_)
#define POS_TH 0.5f
#define NEG_TH 0.4f
#define CAND_CAP 65536
#define SM_CAND 4096
#define CHUNK 64

// ---------------- scratch (static __device__, no allocation) ----------------
__device__ unsigned char      g_mt[ROWS_];      // (gt_idx<<2) | band
__device__ unsigned long long g_gt_best[B_ * N_];
__device__ unsigned long long g_keys[ROWS_];
__device__ signed char        g_conf[ROWS_];
__device__ int                g_hist[2][2048];
__device__ unsigned long long g_cand[CAND_CAP];
__device__ int                g_cand_cnt;
__device__ int                g_work[ROWS_];    // (r<<8) | target
__device__ int                g_work_cnt;
__device__ int                g_num_pos;
__device__ float              g_sl1;
__device__ float              g_ce_sum;
__device__ int                g_done;
__device__ int                g_sel_done;

__device__ __forceinline__ float smooth_l1(float d) {
    float ad = fabsf(d);
    return ad < 1.f ? 0.5f * d * d : ad - 0.5f;
}
__device__ __forceinline__ unsigned ord_bits(float x) {
    unsigned b = __float_as_uint(x);
    unsigned m = (unsigned)((int)b >> 31) | 0x80000000u;
    return b ^ m;   // monotonic float -> uint
}

// parallel digit pick: suffix-scan over 256 thread-group sums, winner resolves
// its 8 digits from registers. 256 threads.
__device__ void pick_digit2(const int* hist, long long Krem_in,
                            int& d_out, long long& Krem_out) {
    __shared__ long long suf[256];
    __shared__ int s_d;
    __shared__ long long s_k;
    int t = threadIdx.x;
    int h[8];
    long long s = 0;
    #pragma unroll
    for (int i = 0; i < 8; i++) { h[i] = hist[t * 8 + i]; s += h[i]; }
    suf[t] = s;
    __syncthreads();
    #pragma unroll
    for (int off = 1; off < 256; off <<= 1) {
        long long v = (t + off < 256) ? suf[t + off] : 0;
        __syncthreads();
        suf[t] += v;
        __syncthreads();
    }
    long long above = (t + 1 < 256) ? suf[t + 1] : 0;
    if (suf[t] >= Krem_in && above < Krem_in) {
        long long ab = above;
        int d = t * 8;
        #pragma unroll
        for (int i = 7; i >= 0; i--) {
            if (ab + h[i] >= Krem_in) { d = t * 8 + i; break; }
            ab += h[i];
        }
        s_d = d; s_k = Krem_in - ab;
    }
    __syncthreads();
    d_out = s_d;
    Krem_out = s_k;
}

// ---------------- K0: per-replay reset ---------------------------------------
__global__ void k_init() {
    int t = threadIdx.x;
    if (t == 0) {
        g_num_pos = 0; g_sl1 = 0.f; g_ce_sum = 0.f;
        g_work_cnt = 0; g_cand_cnt = 0; g_done = 0; g_sel_done = 0;
    }
    for (int i = t; i < 2 * 2048; i += blockDim.x) (&g_hist[0][0])[i] = 0;
    if (t < B_ * N_) g_gt_best[t] = 0x00000000FFFFFFFFull;  // fallback prior 0
}

// ---------------- K1: matching (writes 1B/row band+idx) ----------------------
__global__ void k_match(const float* __restrict__ priors,
                        const float* __restrict__ gt_boxes) {
    int b = blockIdx.y;
    int p = blockIdx.x * 256 + threadIdx.x;

    __shared__ float4 s_gt[N_];
    __shared__ float  s_area[N_];
    __shared__ unsigned long long s_best[N_];
    if (threadIdx.x < N_) {
        float4 g = reinterpret_cast<const float4*>(gt_boxes)[b * N_ + threadIdx.x];
        s_gt[threadIdx.x] = g;
        s_area[threadIdx.x] = (g.z - g.x) * (g.w - g.y);
        s_best[threadIdx.x] = 0ull;
    }
    __syncthreads();

    if (p < P_) {
        float4 pr = reinterpret_cast<const float4*>(priors)[p];
        float px1 = pr.x - pr.z * 0.5f, py1 = pr.y - pr.w * 0.5f;
        float px2 = pr.x + pr.z * 0.5f, py2 = pr.y + pr.w * 0.5f;
        float parea = (px2 - px1) * (py2 - py1);

        float best = 0.f; int bestn = 0;
        #pragma unroll
        for (int n = 0; n < N_; n++) {
            float4 g = s_gt[n];
            float ix1 = fmaxf(px1, g.x), iy1 = fmaxf(py1, g.y);
            float ix2 = fminf(px2, g.z), iy2 = fminf(py2, g.w);
            float iw = fmaxf(ix2 - ix1, 0.f), ih = fmaxf(iy2 - iy1, 0.f);
            float inter = iw * ih;
            float iou = inter / (s_area[n] + parea - inter);
            if (iou > best) { best = iou; bestn = n; }
            if (inter > 0.f) {
                unsigned long long key =
                    (((unsigned long long)__float_as_uint(iou)) << 32) |
                    (unsigned)(~(unsigned)p);
                atomicMax(&s_best[n], key);
            }
        }
        int band = (best < NEG_TH) ? 0 : ((best < POS_TH) ? 1 : 2);
        g_mt[b * P_ + p] = (unsigned char)((bestn << 2) | band);
    }
    __syncthreads();
    if (threadIdx.x < N_)
        atomicMax(&g_gt_best[b * N_ + threadIdx.x], s_best[threadIdx.x]);
}

// ---------------- K2: conf scan (smem-staged) + force-match + loc loss -------
__global__ void __launch_bounds__(256)
k_conf(const float* __restrict__ conf_data,
       const float* __restrict__ loc_data,
       const float* __restrict__ priors,
       const float* __restrict__ gt_boxes,
       const int* __restrict__ gt_labels) {
    const float NINF = __int_as_float(0xff800000);
    __shared__ float s_tile[CHUNK * 81];    // 20736 B
    __shared__ int s_hist[2048];
    __shared__ int s_forced[B_ * N_];
    __shared__ int s_labels[B_ * N_];
    for (int i = threadIdx.x; i < 2048; i += 256) s_hist[i] = 0;
    if (threadIdx.x < B_ * N_) {
        s_forced[threadIdx.x] =
            (int)(~(unsigned)(g_gt_best[threadIdx.x] & 0xFFFFFFFFull));
        s_labels[threadIdx.x] = gt_labels[threadIdx.x];
    }

    const int lane = threadIdx.x & 31;
    const int wrp  = threadIdx.x >> 5;
    const int NCHUNK = ROWS_ / CHUNK;

    float lsl = 0.f;
    int   lnp = 0;

    for (int ch = blockIdx.x; ch < NCHUNK; ch += gridDim.x) {
        const float4* src =
            reinterpret_cast<const float4*>(conf_data + (size_t)ch * CHUNK * 81);
        __syncthreads();
        #pragma unroll 6
        for (int i = threadIdx.x; i < CHUNK * 81 / 4; i += 256)
            reinterpret_cast<float4*>(s_tile)[i] = __ldcs(src + i);
        __syncthreads();

        int r0 = ch * CHUNK + wrp * 8;
        unsigned mr[8];
        #pragma unroll
        for (int j = 0; j < 8; j++) {
            const float* row = s_tile + (wrp * 8 + j) * 81;
            float f = fmaxf(fmaxf(lane ? row[lane] : NINF, row[lane + 32]),
                            (lane < 17) ? row[lane + 64] : NINF);
            mr[j] = __reduce_max_sync(0xffffffffu, ord_bits(f));
        }
        if (lane < 8) {
            unsigned uu = (lane & 4)
                ? ((lane & 2) ? ((lane & 1) ? mr[7] : mr[6])
                              : ((lane & 1) ? mr[5] : mr[4]))
                : ((lane & 2) ? ((lane & 1) ? mr[3] : mr[2])
                              : ((lane & 1) ? mr[1] : mr[0]));
            int r = r0 + lane;
            int b = r / P_;
            int p = r - b * P_;
            unsigned mt = g_mt[r];
            int band = mt & 3;
            int n = mt >> 2;
            #pragma unroll
            for (int n2 = 0; n2 < N_; n2++)
                if (s_forced[b * N_ + n2] == p) { band = 2; n = n2; }
            int c = (band == 0) ? 0 : ((band == 1) ? -1 : s_labels[b * N_ + n]);
            g_conf[r] = (signed char)c;
            unsigned u = (c == 0) ? uu : 0u;
            unsigned long long key =
                (((unsigned long long)u) << 32) | (unsigned)(~(unsigned)r);
            g_keys[r] = key;
            atomicAdd(&s_hist[(int)(key >> 53)], 1);
            if (c > 0) {
                lnp++;
                float4 pr = reinterpret_cast<const float4*>(priors)[p];
                float4 g  = reinterpret_cast<const float4*>(gt_boxes)[b * N_ + n];
                float4 ld = reinterpret_cast<const float4*>(loc_data)[r];
                float tx = ((g.x + g.z) * 0.5f - pr.x) / (0.1f * pr.z);
                float ty = ((g.y + g.w) * 0.5f - pr.y) / (0.1f * pr.w);
                float tw = logf((g.z - g.x) / pr.z) * 5.0f;
                float th = logf((g.w - g.y) / pr.w) * 5.0f;
                lsl += smooth_l1(ld.x - tx) + smooth_l1(ld.y - ty)
                     + smooth_l1(ld.z - tw) + smooth_l1(ld.w - th);
                int pos = atomicAdd(&g_work_cnt, 1);
                g_work[pos] = (r << 8) | c;
            }
        }
    }

    #pragma unroll
    for (int o = 16; o; o >>= 1) {
        lsl += __shfl_xor_sync(0xffffffffu, lsl, o);
        lnp += __shfl_xor_sync(0xffffffffu, lnp, o);
    }
    __shared__ float sf[8];
    __shared__ int   si[8];
    if (lane == 0) { sf[wrp] = lsl; si[wrp] = lnp; }
    __syncthreads();
    if (threadIdx.x == 0) {
        float a = 0.f; int ni = 0;
        #pragma unroll
        for (int i = 0; i < 8; i++) { a += sf[i]; ni += si[i]; }
        if (ni)       atomicAdd(&g_num_pos, ni);
        if (a != 0.f) atomicAdd(&g_sl1, a);
    }
    __syncthreads();
    for (int i = threadIdx.x; i < 2048; i += 256) {
        int v = s_hist[i];
        if (v) atomicAdd(&g_hist[0][i], v);
    }
}

// ---------------- K3: round-2 histogram + definite-keep appends (digit>d1) --
__global__ void __launch_bounds__(256) k_hist2() {
    long long K = 3LL * g_num_pos;
    if (K > ROWS_) K = ROWS_;
    if (K == 0) return;
    long long Krem;
    int d1;
    pick_digit2(g_hist[0], K, d1, Krem);
    unsigned long long D1 = (unsigned long long)d1;

    __shared__ int sh[2048];
    for (int i = threadIdx.x; i < 2048; i += 256) sh[i] = 0;
    __syncthreads();
    const ulonglong2* kp = reinterpret_cast<const ulonglong2*>(g_keys);
    int t = blockIdx.x * 256 + threadIdx.x;
    int stride = gridDim.x * 256;
    for (int i = t; i < ROWS_ / 2; i += stride) {
        ulonglong2 kk = kp[i];
        #pragma unroll
        for (int j = 0; j < 2; j++) {
            unsigned long long key = j ? kk.y : kk.x;
            unsigned long long d = key >> 53;
            if (d == D1) atomicAdd(&sh[(int)((key >> 42) & 2047)], 1);
            else if (d > D1) {   // definitely kept (u>0 => c==0)
                int r = (int)(~(unsigned)(key & 0xFFFFFFFFull));
                int pos = atomicAdd(&g_work_cnt, 1);
                g_work[pos] = r << 8;
            }
        }
    }
    __syncthreads();
    for (int i = threadIdx.x; i < 2048; i += 256) {
        int v = sh[i];
        if (v) atomicAdd(&g_hist[1][i], v);
    }
}

// ---------------- K4: collect ties + appends + last-block exact resolve ------
__global__ void __launch_bounds__(256) k_collect_sel() {
    long long K = 3LL * g_num_pos;
    if (K > ROWS_) K = ROWS_;
    if (K == 0) return;
    long long Krem1, Krem;
    int d1, d2;
    pick_digit2(g_hist[0], K, d1, Krem1);
    pick_digit2(g_hist[1], Krem1, d2, Krem);
    unsigned long long pref = (((unsigned long long)d1) << 11) | (unsigned)d2;

    const ulonglong2* kp = reinterpret_cast<const ulonglong2*>(g_keys);
    int t = blockIdx.x * 256 + threadIdx.x;
    int stride = gridDim.x * 256;
    for (int i = t; i < ROWS_ / 2; i += stride) {
        ulonglong2 kk = kp[i];
        #pragma unroll
        for (int j = 0; j < 2; j++) {
            unsigned long long key = j ? kk.y : kk.x;
            unsigned long long pf = key >> 42;
            if (pf == pref) {
                int pos = atomicAdd(&g_cand_cnt, 1);
                if (pos < CAND_CAP) g_cand[pos] = key;
            } else if (pf > pref && (key >> 53) == (unsigned long long)d1) {
                // kept: same top digit, higher mid digit (u>0 => c==0)
                int r = (int)(~(unsigned)(key & 0xFFFFFFFFull));
                int pos = atomicAdd(&g_work_cnt, 1);
                g_work[pos] = r << 8;
            }
        }
    }

    // last block resolves the final threshold exactly (warp 0, no block syncs)
    __shared__ int s_last;
    __shared__ unsigned long long s_cand[SM_CAND];
    __threadfence();
    if (threadIdx.x == 0)
        s_last = (atomicAdd(&g_sel_done, 1) == (int)gridDim.x - 1);
    __syncthreads();
    if (!s_last) return;

    int cnt = g_cand_cnt;
    if (cnt > CAND_CAP) cnt = CAND_CAP;
    bool in_sm = (cnt <= SM_CAND);
    if (in_sm)
        for (int i = threadIdx.x; i < cnt; i += 256) s_cand[i] = g_cand[i];
    __syncthreads();
    if (threadIdx.x >= 32) return;

    int lane = threadIdx.x;
    unsigned long long F = pref;
    long long Kr = Krem;
    for (int b = 41; b >= 0; b--) {
        int local = 0;
        for (int i = lane; i < cnt; i += 32) {
            unsigned long long k2 = in_sm ? s_cand[i] : g_cand[i];
            if ((k2 >> (b + 1)) == F && ((k2 >> b) & 1ull)) local++;
        }
        int c1 = __reduce_add_sync(0xffffffffu, local);
        if (c1 >= Kr) F = (F << 1) | 1ull;
        else { Kr -= c1; F <<= 1; }
    }
    // append kept candidates (key >= F, background rows only)
    for (int i = lane; i < cnt; i += 32) {
        unsigned long long k2 = in_sm ? s_cand[i] : g_cand[i];
        if (k2 >= F) {
            int r = (int)(~(unsigned)(k2 & 0xFFFFFFFFull));
            if (g_conf[r] == 0) {
                int pos = atomicAdd(&g_work_cnt, 1);
                g_work[pos] = r << 8;
            }
        }
    }
}

// ---------------- K5: CE over compact worklist + output ----------------------
__global__ void __launch_bounds__(256)
k_ce(const float* __restrict__ conf_data, float* __restrict__ out) {
    const float NINF = __int_as_float(0xff800000);
    const int lane = threadIdx.x & 31;
    const int wid  = (blockIdx.x * blockDim.x + threadIdx.x) >> 5;
    const int nw   = (gridDim.x * blockDim.x) >> 5;
    int cnt = g_work_cnt;
    float lce = 0.f;

    for (int i = wid; i < cnt; i += nw) {
        int item = g_work[i];
        int r  = item >> 8;
        int ct = item & 255;
        const float* row = conf_data + (size_t)r * C_;
        float x0 = row[lane];
        float x1 = row[lane + 32];
        float x2 = (lane < 17) ? row[lane + 64] : NINF;
        float m = fmaxf(x0, fmaxf(x1, x2));
        #pragma unroll
        for (int o = 16; o; o >>= 1) m = fmaxf(m, __shfl_xor_sync(0xffffffffu, m, o));
        float s = expf(x0 - m) + expf(x1 - m) + ((lane < 17) ? expf(x2 - m) : 0.f);
        #pragma unroll
        for (int o = 16; o; o >>= 1) s += __shfl_xor_sync(0xffffffffu, s, o);
        float tv = NINF;
        if (lane == ct)                   tv = x0;
        if (lane + 32 == ct)              tv = x1;
        if (lane < 17 && lane + 64 == ct) tv = x2;
        #pragma unroll
        for (int o = 16; o; o >>= 1) tv = fmaxf(tv, __shfl_xor_sync(0xffffffffu, tv, o));
        if (lane == 0) lce += (m + logf(s)) - tv;
    }

    #pragma unroll
    for (int o = 16; o; o >>= 1) lce += __shfl_xor_sync(0xffffffffu, lce, o);
    __shared__ float sf[8];
    int w = threadIdx.x >> 5;
    if (lane == 0) sf[w] = lce;
    __syncthreads();
    if (threadIdx.x == 0) {
        float a = 0.f;
        #pragma unroll
        for (int i = 0; i < 8; i++) a += sf[i];
        if (a != 0.f) atomicAdd(&g_ce_sum, a);
        __threadfence();
        int done = atomicAdd(&g_done, 1);
        if (done == (int)gridDim.x - 1) {
            int np = g_num_pos; if (np < 1) np = 1;
            int kp = cnt;       if (kp < 1) kp = 1;
            out[0] = g_sl1    / (float)np;
            out[1] = g_ce_sum / (float)kp;
        }
    }
}

// ---------------- host -------------------------------------------------------
extern "C" void kernel_launch(void* const* d_in, const int* in_sizes, int n_in,
                              void* d_out, int out_size) {
    const float* loc = nullptr;
    const float* conf = nullptr;
    const float* priors = nullptr;
    const float* gtb = nullptr;
    const int*   gtl = nullptr;
    for (int i = 0; i < n_in; i++) {
        long long s = in_sizes[i];
        if      (s == (long long)B_ * P_ * C_) conf   = (const float*)d_in[i];
        else if (s == (long long)B_ * P_ * 4)  loc    = (const float*)d_in[i];
        else if (s == (long long)P_ * 4)       priors = (const float*)d_in[i];
        else if (s == (long long)B_ * N_ * 4)  gtb    = (const float*)d_in[i];
        else if (s == (long long)B_ * N_)      gtl    = (const int*)d_in[i];
    }
    float* out = (float*)d_out;

    k_init<<<1, 1024>>>();
    k_match<<<dim3((P_ + 255) / 256, B_), 256>>>(priors, gtb);
    k_conf<<<1776, 256>>>(conf, loc, priors, gtb, gtl);
    k_hist2<<<888, 256>>>();
    k_collect_sel<<<888, 256>>>();
    k_ce<<<464, 256>>>(conf, out);
}

// round 6
// speedup vs baseline: 1.0928x; 1.0928x over previous
#include <cuda_runtime.h>

#define B_ 8
#define P_ 57744
#define C_ 81
#define N_ 20
#define ROWS_ (B_ * P_)
#define POS_TH 0.5f
#define NEG_TH 0.4f
#define CAND_CAP 131072
#define CAND2_CAP 16384
#define SM_CAND 4096

// ---------------- scratch (static __device__, no allocation) ----------------
__device__ unsigned char      g_mt[ROWS_];      // (gt_idx<<2) | band
__device__ unsigned long long g_gt_best[B_ * N_];
__device__ unsigned long long g_keys[ROWS_];
__device__ signed char        g_conf[ROWS_];
__device__ int                g_hist0[8192];
__device__ int                g_hist1[2048];
__device__ unsigned long long g_cand[CAND_CAP];
__device__ unsigned long long g_cand2[CAND2_CAP];
__device__ int                g_cand_cnt;
__device__ int                g_cand2_cnt;
__device__ int                g_work[ROWS_];    // (r<<8) | target
__device__ int                g_work_cnt;
__device__ int                g_num_pos;
__device__ int                g_K;
__device__ int                g_d1;
__device__ long long          g_Krem1;
__device__ int                g_d2;
__device__ long long          g_Krem2;
__device__ float              g_sl1;
__device__ float              g_ce_sum;
__device__ int                g_done_conf;
__device__ int                g_done_s1;
__device__ int                g_done_s2;
__device__ int                g_done_ce;

__device__ __forceinline__ float smooth_l1(float d) {
    float ad = fabsf(d);
    return ad < 1.f ? 0.5f * d * d : ad - 0.5f;
}
__device__ __forceinline__ unsigned ord_bits(float x) {
    unsigned b = __float_as_uint(x);
    unsigned m = (unsigned)((int)b >> 31) | 0x80000000u;
    return b ^ m;   // monotonic float -> uint
}

// suffix-scan based pick over NB buckets (NB/256 per thread), 256 threads.
template <int GPT>   // groups per thread
__device__ void pick_digitN(const int* hist, long long Krem_in,
                            int& d_out, long long& Krem_out) {
    __shared__ long long suf[256];
    __shared__ int s_d;
    __shared__ long long s_k;
    int t = threadIdx.x;
    int h[GPT];
    long long s = 0;
    #pragma unroll
    for (int i = 0; i < GPT; i++) { h[i] = hist[t * GPT + i]; s += h[i]; }
    suf[t] = s;
    __syncthreads();
    #pragma unroll
    for (int off = 1; off < 256; off <<= 1) {
        long long v = (t + off < 256) ? suf[t + off] : 0;
        __syncthreads();
        suf[t] += v;
        __syncthreads();
    }
    long long above = (t + 1 < 256) ? suf[t + 1] : 0;
    if (suf[t] >= Krem_in && above < Krem_in) {
        long long ab = above;
        int d = t * GPT;
        #pragma unroll
        for (int i = GPT - 1; i >= 0; i--) {
            if (ab + h[i] >= Krem_in) { d = t * GPT + i; break; }
            ab += h[i];
        }
        s_d = d; s_k = Krem_in - ab;
    }
    __syncthreads();
    d_out = s_d;
    Krem_out = s_k;
}

// ---------------- K0: per-replay reset ---------------------------------------
__global__ void k_init() {
    int t = blockIdx.x * 1024 + threadIdx.x;
    if (t == 0) {
        g_num_pos = 0; g_sl1 = 0.f; g_ce_sum = 0.f;
        g_work_cnt = 0; g_cand_cnt = 0; g_cand2_cnt = 0;
        g_done_conf = 0; g_done_s1 = 0; g_done_s2 = 0; g_done_ce = 0;
    }
    if (t < 8192) g_hist0[t] = 0;
    if (t < 2048) g_hist1[t] = 0;
    if (t < B_ * N_) g_gt_best[t] = 0x00000000FFFFFFFFull;  // fallback prior 0
}

// ---------------- K1: matching (writes 1B/row band+idx) ----------------------
__global__ void k_match(const float* __restrict__ priors,
                        const float* __restrict__ gt_boxes) {
    int b = blockIdx.y;
    int p = blockIdx.x * 256 + threadIdx.x;

    __shared__ float4 s_gt[N_];
    __shared__ float  s_area[N_];
    __shared__ unsigned long long s_best[N_];
    if (threadIdx.x < N_) {
        float4 g = reinterpret_cast<const float4*>(gt_boxes)[b * N_ + threadIdx.x];
        s_gt[threadIdx.x] = g;
        s_area[threadIdx.x] = (g.z - g.x) * (g.w - g.y);
        s_best[threadIdx.x] = 0ull;
    }
    __syncthreads();

    if (p < P_) {
        float4 pr = reinterpret_cast<const float4*>(priors)[p];
        float px1 = pr.x - pr.z * 0.5f, py1 = pr.y - pr.w * 0.5f;
        float px2 = pr.x + pr.z * 0.5f, py2 = pr.y + pr.w * 0.5f;
        float parea = (px2 - px1) * (py2 - py1);

        float best = 0.f; int bestn = 0;
        #pragma unroll
        for (int n = 0; n < N_; n++) {
            float4 g = s_gt[n];
            float ix1 = fmaxf(px1, g.x), iy1 = fmaxf(py1, g.y);
            float ix2 = fminf(px2, g.z), iy2 = fminf(py2, g.w);
            float iw = fmaxf(ix2 - ix1, 0.f), ih = fmaxf(iy2 - iy1, 0.f);
            float inter = iw * ih;
            float iou = inter / (s_area[n] + parea - inter);
            if (iou > best) { best = iou; bestn = n; }
            if (inter > 0.f) {
                unsigned long long key =
                    (((unsigned long long)__float_as_uint(iou)) << 32) |
                    (unsigned)(~(unsigned)p);
                atomicMax(&s_best[n], key);
            }
        }
        int band = (best < NEG_TH) ? 0 : ((best < POS_TH) ? 1 : 2);
        g_mt[b * P_ + p] = (unsigned char)((bestn << 2) | band);
    }
    __syncthreads();
    if (threadIdx.x < N_)
        atomicMax(&g_gt_best[b * N_ + threadIdx.x], s_best[threadIdx.x]);
}

// ---------------- K2: conf scan + force-match + loc loss + hist0 + pick d1 ---
__global__ void __launch_bounds__(256)
k_conf(const float* __restrict__ conf_data,
       const float* __restrict__ loc_data,
       const float* __restrict__ priors,
       const float* __restrict__ gt_boxes,
       const int* __restrict__ gt_labels) {
    const float NINF = __int_as_float(0xff800000);
    __shared__ int s_hist[8192];
    __shared__ int s_forced[B_ * N_];
    __shared__ int s_labels[B_ * N_];
    for (int i = threadIdx.x; i < 8192; i += 256) s_hist[i] = 0;
    if (threadIdx.x < B_ * N_) {
        s_forced[threadIdx.x] =
            (int)(~(unsigned)(g_gt_best[threadIdx.x] & 0xFFFFFFFFull));
        s_labels[threadIdx.x] = gt_labels[threadIdx.x];
    }
    __syncthreads();

    const int lane = threadIdx.x & 31;
    const int wid  = (blockIdx.x * blockDim.x + threadIdx.x) >> 5;
    const int nw   = (gridDim.x * blockDim.x) >> 5;

    float lsl = 0.f;
    int   lnp = 0;
    const int NCH = ROWS_ / 8;

    for (int ch = wid; ch < NCH; ch += nw) {
        int r0 = ch * 8;
        const float* base = conf_data + (size_t)r0 * C_;
        float xa[8], xb[8], xc[8];
        #pragma unroll
        for (int j = 0; j < 8; j++) {
            const float* row = base + j * C_;
            xa[j] = __ldcs(row + lane);
            xb[j] = __ldcs(row + lane + 32);
            xc[j] = (lane < 17) ? __ldcs(row + lane + 64) : NINF;
        }
        unsigned mr[8];
        #pragma unroll
        for (int j = 0; j < 8; j++) {
            float f = fmaxf(fmaxf(lane ? xa[j] : NINF, xb[j]),
                            (lane < 17) ? xc[j] : NINF);
            mr[j] = __reduce_max_sync(0xffffffffu, ord_bits(f));
        }
        if (lane < 8) {
            unsigned uu = (lane & 4)
                ? ((lane & 2) ? ((lane & 1) ? mr[7] : mr[6])
                              : ((lane & 1) ? mr[5] : mr[4]))
                : ((lane & 2) ? ((lane & 1) ? mr[3] : mr[2])
                              : ((lane & 1) ? mr[1] : mr[0]));
            int r = r0 + lane;
            int b = r / P_;
            int p = r - b * P_;
            unsigned mt = g_mt[r];
            int band = mt & 3;
            int n = mt >> 2;
            #pragma unroll
            for (int n2 = 0; n2 < N_; n2++)
                if (s_forced[b * N_ + n2] == p) { band = 2; n = n2; }
            int c = (band == 0) ? 0 : ((band == 1) ? -1 : s_labels[b * N_ + n]);
            g_conf[r] = (signed char)c;
            unsigned u = (c == 0) ? uu : 0u;
            unsigned long long key =
                (((unsigned long long)u) << 32) | (unsigned)(~(unsigned)r);
            g_keys[r] = key;
            atomicAdd(&s_hist[(int)(key >> 51)], 1);
            if (c > 0) {
                lnp++;
                float4 pr = reinterpret_cast<const float4*>(priors)[p];
                float4 g  = reinterpret_cast<const float4*>(gt_boxes)[b * N_ + n];
                float4 ld = reinterpret_cast<const float4*>(loc_data)[r];
                float tx = ((g.x + g.z) * 0.5f - pr.x) / (0.1f * pr.z);
                float ty = ((g.y + g.w) * 0.5f - pr.y) / (0.1f * pr.w);
                float tw = logf((g.z - g.x) / pr.z) * 5.0f;
                float th = logf((g.w - g.y) / pr.w) * 5.0f;
                lsl += smooth_l1(ld.x - tx) + smooth_l1(ld.y - ty)
                     + smooth_l1(ld.z - tw) + smooth_l1(ld.w - th);
                int pos = atomicAdd(&g_work_cnt, 1);
                g_work[pos] = (r << 8) | c;
            }
        }
    }

    #pragma unroll
    for (int o = 16; o; o >>= 1) {
        lsl += __shfl_xor_sync(0xffffffffu, lsl, o);
        lnp += __shfl_xor_sync(0xffffffffu, lnp, o);
    }
    __shared__ float sf[8];
    __shared__ int   si[8];
    int w = threadIdx.x >> 5;
    if (lane == 0) { sf[w] = lsl; si[w] = lnp; }
    __syncthreads();
    if (threadIdx.x == 0) {
        float a = 0.f; int ni = 0;
        #pragma unroll
        for (int i = 0; i < 8; i++) { a += sf[i]; ni += si[i]; }
        if (ni)       atomicAdd(&g_num_pos, ni);
        if (a != 0.f) atomicAdd(&g_sl1, a);
    }
    __syncthreads();
    for (int i = threadIdx.x; i < 8192; i += 256) {
        int v = s_hist[i];
        if (v) atomicAdd(&g_hist0[i], v);
    }

    // last block picks d1 (free pick, no extra launch)
    __shared__ int s_last;
    __threadfence();
    if (threadIdx.x == 0)
        s_last = (atomicAdd(&g_done_conf, 1) == (int)gridDim.x - 1);
    __syncthreads();
    if (!s_last) return;
    long long K = 3LL * g_num_pos;
    if (K > ROWS_) K = ROWS_;
    if (threadIdx.x == 0) g_K = (int)K;
    if (K == 0) return;
    int d1; long long kr;
    pick_digitN<32>(g_hist0, K, d1, kr);
    if (threadIdx.x == 0) { g_d1 = d1; g_Krem1 = kr; }
}

// ---------------- K3: full-key scan: keeps (>d1), cands (==d1) + hist1 -------
__global__ void __launch_bounds__(256) k_scan1() {
    if (g_K == 0) return;
    const unsigned long long D1 = (unsigned long long)g_d1;
    __shared__ int sh[2048];
    for (int i = threadIdx.x; i < 2048; i += 256) sh[i] = 0;
    __syncthreads();

    const ulonglong2* kp = reinterpret_cast<const ulonglong2*>(g_keys);
    int t = blockIdx.x * 256 + threadIdx.x;
    int stride = gridDim.x * 256;
    for (int i = t; i < ROWS_ / 2; i += stride) {
        ulonglong2 kk = kp[i];
        #pragma unroll
        for (int j = 0; j < 2; j++) {
            unsigned long long key = j ? kk.y : kk.x;
            unsigned long long d = key >> 51;
            if (d == D1) {
                int pos = atomicAdd(&g_cand_cnt, 1);
                if (pos < CAND_CAP) g_cand[pos] = key;
                atomicAdd(&sh[(int)((key >> 40) & 2047)], 1);
            } else if (d > D1) {   // u>0 => c==0: definitely kept
                int r = (int)(~(unsigned)(key & 0xFFFFFFFFull));
                int pos = atomicAdd(&g_work_cnt, 1);
                g_work[pos] = r << 8;
            }
        }
    }
    __syncthreads();
    for (int i = threadIdx.x; i < 2048; i += 256) {
        int v = sh[i];
        if (v) atomicAdd(&g_hist1[i], v);
    }

    // last block picks d2
    __shared__ int s_last;
    __threadfence();
    if (threadIdx.x == 0)
        s_last = (atomicAdd(&g_done_s1, 1) == (int)gridDim.x - 1);
    __syncthreads();
    if (!s_last) return;
    int d2; long long kr;
    pick_digitN<8>(g_hist1, g_Krem1, d2, kr);
    if (threadIdx.x == 0) { g_d2 = d2; g_Krem2 = kr; }
}

// ---------------- K4: cand scan: keeps (>d2), ties (==d2) + exact resolve ----
__global__ void __launch_bounds__(256) k_scan2() {
    if (g_K == 0) return;
    const unsigned long long D2 = (unsigned long long)g_d2;
    int cnt = g_cand_cnt;
    if (cnt > CAND_CAP) cnt = CAND_CAP;

    int t = blockIdx.x * 256 + threadIdx.x;
    int stride = gridDim.x * 256;
    for (int i = t; i < cnt; i += stride) {
        unsigned long long key = g_cand[i];
        unsigned long long mid = (key >> 40) & 2047;
        if (mid == D2) {
            int pos = atomicAdd(&g_cand2_cnt, 1);
            if (pos < CAND2_CAP) g_cand2[pos] = key;
        } else if (mid > D2) {
            int r = (int)(~(unsigned)(key & 0xFFFFFFFFull));
            if (g_conf[r] == 0) {
                int pos = atomicAdd(&g_work_cnt, 1);
                g_work[pos] = r << 8;
            }
        }
    }

    // last block: exact resolve of remaining 40 bits (warp 0)
    __shared__ int s_last;
    __shared__ unsigned long long s_cand[SM_CAND];
    __threadfence();
    if (threadIdx.x == 0)
        s_last = (atomicAdd(&g_done_s2, 1) == (int)gridDim.x - 1);
    __syncthreads();
    if (!s_last) return;

    int c2 = g_cand2_cnt;
    if (c2 > CAND2_CAP) c2 = CAND2_CAP;
    bool in_sm = (c2 <= SM_CAND);
    if (in_sm)
        for (int i = threadIdx.x; i < c2; i += 256) s_cand[i] = g_cand2[i];
    __syncthreads();
    if (threadIdx.x >= 32) return;

    int lane = threadIdx.x;
    unsigned long long F =
        (((unsigned long long)g_d1) << 11) | (unsigned long long)g_d2;
    long long Kr = g_Krem2;
    for (int b = 39; b >= 0; b--) {
        int local = 0;
        for (int i = lane; i < c2; i += 32) {
            unsigned long long k2 = in_sm ? s_cand[i] : g_cand2[i];
            if ((k2 >> (b + 1)) == F && ((k2 >> b) & 1ull)) local++;
        }
        int c1 = __reduce_add_sync(0xffffffffu, local);
        if (c1 >= Kr) F = (F << 1) | 1ull;
        else { Kr -= c1; F <<= 1; }
    }
    for (int i = lane; i < c2; i += 32) {
        unsigned long long k2 = in_sm ? s_cand[i] : g_cand2[i];
        if (k2 >= F) {
            int r = (int)(~(unsigned)(k2 & 0xFFFFFFFFull));
            if (g_conf[r] == 0) {
                int pos = atomicAdd(&g_work_cnt, 1);
                g_work[pos] = r << 8;
            }
        }
    }
}

// ---------------- K5: CE over compact worklist + output ----------------------
__global__ void __launch_bounds__(256)
k_ce(const float* __restrict__ conf_data, float* __restrict__ out) {
    const float NINF = __int_as_float(0xff800000);
    const int lane = threadIdx.x & 31;
    const int wid  = (blockIdx.x * blockDim.x + threadIdx.x) >> 5;
    const int nw   = (gridDim.x * blockDim.x) >> 5;
    int cnt = g_work_cnt;
    float lce = 0.f;

    for (int i = wid; i < cnt; i += nw) {
        int item = g_work[i];
        int r  = item >> 8;
        int ct = item & 255;
        const float* row = conf_data + (size_t)r * C_;
        float x0 = row[lane];
        float x1 = row[lane + 32];
        float x2 = (lane < 17) ? row[lane + 64] : NINF;
        float m = fmaxf(x0, fmaxf(x1, x2));
        #pragma unroll
        for (int o = 16; o; o >>= 1) m = fmaxf(m, __shfl_xor_sync(0xffffffffu, m, o));
        float s = expf(x0 - m) + expf(x1 - m) + ((lane < 17) ? expf(x2 - m) : 0.f);
        #pragma unroll
        for (int o = 16; o; o >>= 1) s += __shfl_xor_sync(0xffffffffu, s, o);
        float tv = NINF;
        if (lane == ct)                   tv = x0;
        if (lane + 32 == ct)              tv = x1;
        if (lane < 17 && lane + 64 == ct) tv = x2;
        #pragma unroll
        for (int o = 16; o; o >>= 1) tv = fmaxf(tv, __shfl_xor_sync(0xffffffffu, tv, o));
        if (lane == 0) lce += (m + logf(s)) - tv;
    }

    #pragma unroll
    for (int o = 16; o; o >>= 1) lce += __shfl_xor_sync(0xffffffffu, lce, o);
    __shared__ float sf[8];
    int w = threadIdx.x >> 5;
    if (lane == 0) sf[w] = lce;
    __syncthreads();
    if (threadIdx.x == 0) {
        float a = 0.f;
        #pragma unroll
        for (int i = 0; i < 8; i++) a += sf[i];
        if (a != 0.f) atomicAdd(&g_ce_sum, a);
        __threadfence();
        int done = atomicAdd(&g_done_ce, 1);
        if (done == (int)gridDim.x - 1) {
            int np = g_num_pos; if (np < 1) np = 1;
            int kp = cnt;       if (kp < 1) kp = 1;
            out[0] = g_sl1    / (float)np;
            out[1] = g_ce_sum / (float)kp;
        }
    }
}

// ---------------- host -------------------------------------------------------
extern "C" void kernel_launch(void* const* d_in, const int* in_sizes, int n_in,
                              void* d_out, int out_size) {
    const float* loc = nullptr;
    const float* conf = nullptr;
    const float* priors = nullptr;
    const float* gtb = nullptr;
    const int*   gtl = nullptr;
    for (int i = 0; i < n_in; i++) {
        long long s = in_sizes[i];
        if      (s == (long long)B_ * P_ * C_) conf   = (const float*)d_in[i];
        else if (s == (long long)B_ * P_ * 4)  loc    = (const float*)d_in[i];
        else if (s == (long long)P_ * 4)       priors = (const float*)d_in[i];
        else if (s == (long long)B_ * N_ * 4)  gtb    = (const float*)d_in[i];
        else if (s == (long long)B_ * N_)      gtl    = (const int*)d_in[i];
    }
    float* out = (float*)d_out;

    k_init<<<8, 1024>>>();
    k_match<<<dim3((P_ + 255) / 256, B_), 256>>>(priors, gtb);
    k_conf<<<1776, 256>>>(conf, loc, priors, gtb, gtl);
    k_scan1<<<296, 256>>>();
    k_scan2<<<148, 256>>>();
    k_ce<<<464, 256>>>(conf, out);
}